// round 16
// baseline (speedup 1.0000x reference)
#include <cuda_runtime.h>

// QPIELayer single-kernel, register-resident state, one-wave tiling.
// 16-qubit circuit reduced to 10 live qubits (8 system + 2 ancilla); records
// are write-once / read-once-as-control and traced by the diagonal
// measurement, so each layer boundary is an incoherent 4-way branch split.
//
// 128 CTAs = (batch 16) x (layer-1 branch 4) x (layer-2 branch-pair 2):
// exactly one wave on 148 SMs. Each CTA recomputes layers 0/1 for its branch
// path (4 float2 regs/thread), then carries TWO layer-2 branches at once
// (8 float2 regs/thread -> 8-wide ILP on every shuffle/FMA chain).
//
// Amp index i = (a << 8) | tid:  a = ancilla bits -> register index,
// tid bits 0..4 = lane (gates via __shfl_xor), bits 5..7 = warp (gates via
// conflict-free smem exchange). Ancilla block is pure register math.

#define NTH 256

__device__ float        g_ev[128 * 8];   // per-CTA EV partials
__device__ unsigned int g_tk[16];        // per-batch monotonic tickets

__device__ __forceinline__ float2 cmul(float2 a, float2 b) {
    return make_float2(a.x * b.x - a.y * b.y, a.x * b.y + a.y * b.x);
}
__device__ __forceinline__ float2 cmac(float2 a, float2 b, float2 c) {   // a*b + c
    return make_float2(fmaf(a.x, b.x, fmaf(-a.y, b.y, c.x)),
                       fmaf(a.x, b.y, fmaf( a.y, b.x, c.y)));
}
__device__ __forceinline__ float2 cconj(float2 a) { return make_float2(a.x, -a.y); }
__device__ __forceinline__ float2 cadd(float2 a, float2 b) { return make_float2(a.x + b.x, a.y + b.y); }
__device__ __forceinline__ float2 csub(float2 a, float2 b) { return make_float2(a.x - b.x, a.y - b.y); }
__device__ __forceinline__ float2 chalf(float2 a) { return make_float2(0.5f * a.x, 0.5f * a.y); }

__device__ __forceinline__ float2 shfl_xor2(float2 v, int m) {
    v.x = __shfl_xor_sync(0xffffffffu, v.x, m);
    v.y = __shfl_xor_sync(0xffffffffu, v.y, m);
    return v;
}

// ---- single-qubit gate on lane bit B (B <= 4) ------------------------------
template<int B, int NR>
__device__ __forceinline__ void gate1_sh(float2* r, const float2* U) {
    const int bit = (threadIdx.x >> B) & 1;
    const float2 ua = bit ? U[3] : U[0];     // coef on own amp
    const float2 ub = bit ? U[2] : U[1];     // coef on partner amp
#pragma unroll
    for (int a = 0; a < NR; ++a) {
        float2 p = shfl_xor2(r[a], 1 << B);
        r[a] = cmac(ua, r[a], cmul(ub, p));
    }
}

// ---- three fused single-qubit gates on warp bits 5,6,7 (one smem exchange) -
template<int NR>
__device__ __forceinline__ void gate3_high(float2* r, float2 (*buf)[NTH],
                                           const float2* U5, const float2* U6,
                                           const float2* U7) {
    const int tid = threadIdx.x;
    const int w = tid >> 5, lane = tid & 31;
    const int b5 = w & 1, b6 = (w >> 1) & 1, b7 = (w >> 2) & 1;
    float2 M[8];                              // own row of U7 (x) U6 (x) U5
#pragma unroll
    for (int wp = 0; wp < 8; ++wp) {
        float2 m = cmul(U5[b5 * 2 + (wp & 1)], U6[b6 * 2 + ((wp >> 1) & 1)]);
        M[wp] = cmul(m, U7[b7 * 2 + ((wp >> 2) & 1)]);
    }
#pragma unroll
    for (int a = 0; a < NR; ++a) buf[a][tid] = r[a];
    __syncthreads();
#pragma unroll
    for (int a = 0; a < NR; ++a) {
        float2 acc = make_float2(0.f, 0.f);
#pragma unroll
        for (int wp = 0; wp < 8; ++wp)
            acc = cmac(M[wp], buf[a][wp * 32 + lane], acc);
        r[a] = acc;
    }
    __syncthreads();
}

// ---- fused RZZ*RYY*RXX on (B1,B2): each amp mixes with ONE partner ---------
// pc = {K=cos((t1-t2)/2), Lc=-sin((t1-t2)/2), K2=cos((t1+t2)/2),
//       L2=sin((t1+t2)/2), ec=cos(t3/2), es=sin(t3/2)}
template<int NR>
__device__ __forceinline__ void pair_core(float2* r, const float2* p,
                                          float Kc, float S, float2 ph) {
#pragma unroll
    for (int a = 0; a < NR; ++a) {
        float2 t = make_float2(Kc * r[a].x - S * p[a].y, Kc * r[a].y + S * p[a].x);
        r[a] = cmul(ph, t);
    }
}

template<int B1, int B2, int NR>
__device__ __forceinline__ void pair_sh(float2* r, const float* pc) {
    const int pr = ((threadIdx.x >> B1) ^ (threadIdx.x >> B2)) & 1;
    const float Kc = pr ? pc[2] : pc[0];
    const float S  = pr ? -pc[3] : pc[1];
    const float2 ph = make_float2(pc[4], pr ? pc[5] : -pc[5]);
    float2 p[NR];
#pragma unroll
    for (int a = 0; a < NR; ++a) p[a] = shfl_xor2(r[a], (1 << B1) | (1 << B2));
    pair_core<NR>(r, p, Kc, S, ph);
}

template<int B1, int B2, int NR>
__device__ __forceinline__ void pair_sm(float2* r, float2 (*buf)[NTH], const float* pc) {
    const int tid = threadIdx.x;
    const int ptid = tid ^ ((1 << B1) | (1 << B2));
    const int pr = ((tid >> B1) ^ (tid >> B2)) & 1;
    const float Kc = pr ? pc[2] : pc[0];
    const float S  = pr ? -pc[3] : pc[1];
    const float2 ph = make_float2(pc[4], pr ? pc[5] : -pc[5]);
#pragma unroll
    for (int a = 0; a < NR; ++a) buf[a][tid] = r[a];
    __syncthreads();
    float2 p[NR];
#pragma unroll
    for (int a = 0; a < NR; ++a) p[a] = buf[a][ptid];
    pair_core<NR>(r, p, Kc, S, ph);
    __syncthreads();
}

// ---- CCRX(pi/4): controls = anc bit ABIT (of reg index) + tid bit B1;
//      target = tid bit B2. Anc bits are the low 2 bits of the reg index,
//      so (a & ABIT) selects control-set registers for every carried branch.
template<int B1, int B2, int ABIT, int NR>
__device__ __forceinline__ void ccrx_sh(float2* r) {
    const float cc = 0.92387953251128675613f;   // cos(pi/8)
    const float ss = 0.38268343236508977173f;   // sin(pi/8)
    const int ctrl = (threadIdx.x >> B1) & 1;
#pragma unroll
    for (int a = 0; a < NR; ++a) {
        if (a & ABIT) {
            float2 p = shfl_xor2(r[a], 1 << B2);
            if (ctrl)
                r[a] = make_float2(cc * r[a].x + ss * p.y, cc * r[a].y - ss * p.x);
        }
    }
}

// ---- ancilla block, pure registers: (H(x)H), CRZ diag, (H(x)H if ODD) ------
template<int ODD, int NB>
__device__ __forceinline__ void anc_reg(float2* rr, const float* pwh) {
    const int s = threadIdx.x;
    float d0 = 0.0f, d1 = 0.0f;
#pragma unroll
    for (int j = 0; j < 8; ++j)
        if ((s >> j) & 1) { d0 += pwh[j]; d1 += pwh[8 + j]; }
    float sp, cp, sm, cm;
    sincosf(d0 + d1, &sp, &cp);
    sincosf(d0 - d1, &sm, &cm);
    const float2 P = make_float2(cp, sp), M = make_float2(cm, sm);
#pragma unroll
    for (int b = 0; b < NB; ++b) {
        float2* r = rr + 4 * b;
        float2 v0 = chalf(cadd(cadd(r[0], r[1]), cadd(r[2], r[3])));
        float2 v1 = chalf(cadd(csub(r[0], r[1]), csub(r[2], r[3])));
        float2 v2 = chalf(csub(cadd(r[0], r[1]), cadd(r[2], r[3])));
        float2 v3 = chalf(cadd(csub(r[0], r[1]), csub(r[3], r[2])));
        r[0] = cmul(cconj(P), v0);
        r[1] = cmul(M,        v1);
        r[2] = cmul(cconj(M), v2);
        r[3] = cmul(P,        v3);
        if (ODD) {
            float2 y0 = chalf(cadd(cadd(r[0], r[1]), cadd(r[2], r[3])));
            float2 y1 = chalf(cadd(csub(r[0], r[1]), csub(r[2], r[3])));
            float2 y2 = chalf(csub(cadd(r[0], r[1]), cadd(r[2], r[3])));
            float2 y3 = chalf(cadd(csub(r[0], r[1]), csub(r[3], r[2])));
            r[0] = y0; r[1] = y1; r[2] = y2; r[3] = y3;
        }
    }
}

// ---- one full layer --------------------------------------------------------
template<int L, int NR>
__device__ __forceinline__ void simLayer(float2* r, float2 (*buf)[NTH],
                                         const float* x, int batch,
                                         const float* w, const float* pw,
                                         float2 (*rotU)[4], float2 (*vwU)[4],
                                         float (*pco)[6], float* pwh) {
    const float* wl  = w  + L * 48;
    const float* pwl = pw + L * 16;
    const int tid = threadIdx.x;
    const float R = 0.70710678118654752440f;

    if (tid < 8) {                               // per-qubit rot (RY even / RX odd)
        float s, c;
        sincosf(0.5f * x[batch * 8 + tid], &s, &c);
        float2 u00, u01, u10, u11;
        if ((L & 1) == 0) {
            u00 = make_float2(c, 0); u01 = make_float2(-s, 0);
            u10 = make_float2(s, 0); u11 = make_float2(c, 0);
        } else {
            u00 = make_float2(c, 0); u01 = make_float2(0, -s);
            u10 = make_float2(0, -s); u11 = make_float2(c, 0);
        }
        if (L == 0) {   // fold initial H: U <- U @ H
            float2 v00 = make_float2(R * (u00.x + u01.x), R * (u00.y + u01.y));
            float2 v01 = make_float2(R * (u00.x - u01.x), R * (u00.y - u01.y));
            float2 v10 = make_float2(R * (u10.x + u11.x), R * (u10.y + u11.y));
            float2 v11 = make_float2(R * (u10.x - u11.x), R * (u10.y - u11.y));
            u00 = v00; u01 = v01; u10 = v10; u11 = v11;
        }
        rotU[tid][0] = u00; rotU[tid][1] = u01; rotU[tid][2] = u10; rotU[tid][3] = u11;
    } else if (tid < 16) {                       // fused RZ*RY*RX (vw block)
        int q = tid - 8;
        float t1 = wl[24 + 3 * q], t2 = wl[25 + 3 * q], t3 = wl[26 + 3 * q];
        float s1, c1, s2, c2, es, ec;
        sincosf(0.5f * t1, &s1, &c1);
        sincosf(0.5f * t2, &s2, &c2);
        sincosf(0.5f * t3, &es, &ec);
        float2 a00 = make_float2(c1 * c2,  s1 * s2);
        float2 a01 = make_float2(-s2 * c1, -c2 * s1);
        float2 a10 = make_float2( s2 * c1, -c2 * s1);
        float2 a11 = make_float2(c1 * c2, -s1 * s2);
        float2 e = make_float2(ec, -es);
        vwU[q][0] = cmul(e, a00); vwU[q][1] = cmul(e, a01);
        vwU[q][2] = cmul(cconj(e), a10); vwU[q][3] = cmul(cconj(e), a11);
    } else if (tid < 23) {                       // pair-gate coefficients
        int i = tid - 16;
        float t1 = wl[3 * i], t2 = wl[3 * i + 1], t3 = wl[3 * i + 2];
        float sd, cd, s2, c2, es, ec;
        sincosf(0.5f * (t1 - t2), &sd, &cd);
        sincosf(0.5f * (t1 + t2), &s2, &c2);
        sincosf(0.5f * t3, &es, &ec);
        pco[i][0] = cd; pco[i][1] = -sd; pco[i][2] = c2; pco[i][3] = s2;
        pco[i][4] = ec; pco[i][5] = es;
    } else if (tid >= 32 && tid < 48) {
        pwh[tid - 32] = 0.5f * pwl[tid - 32];
    }
    __syncthreads();

    // per-qubit rotations (all single-qubit gates commute)
    gate1_sh<0, NR>(r, rotU[0]);
    gate1_sh<1, NR>(r, rotU[1]);
    gate1_sh<2, NR>(r, rotU[2]);
    gate1_sh<3, NR>(r, rotU[3]);
    gate1_sh<4, NR>(r, rotU[4]);
    gate3_high<NR>(r, buf, rotU[5], rotU[6], rotU[7]);

    anc_reg<(L & 1), NR / 4>(r, pwh);

    // entangling pairs: disjoint group first (order-safe), then offset group
    pair_sh<0, 1, NR>(r, pco[0]);  ccrx_sh<0, 1, 1, NR>(r);   // ctrl anc0
    pair_sh<2, 3, NR>(r, pco[1]);  ccrx_sh<2, 3, 2, NR>(r);   // ctrl anc1
    pair_sm<4, 5, NR>(r, buf, pco[2]);
    pair_sm<6, 7, NR>(r, buf, pco[3]);
    pair_sh<1, 2, NR>(r, pco[4]);
    pair_sh<3, 4, NR>(r, pco[5]);
    pair_sm<5, 6, NR>(r, buf, pco[6]);

    // fused RZ*RY*RX per system qubit
    gate1_sh<0, NR>(r, vwU[0]);
    gate1_sh<1, NR>(r, vwU[1]);
    gate1_sh<2, NR>(r, vwU[2]);
    gate1_sh<3, NR>(r, vwU[3]);
    gate1_sh<4, NR>(r, vwU[4]);
    gate3_high<NR>(r, buf, vwU[5], vwU[6], vwU[7]);
}

__global__ void __launch_bounds__(NTH)
qpie_all(const float* __restrict__ x, const float* __restrict__ w,
         const float* __restrict__ pw, float* __restrict__ out) {
    __shared__ float2 buf[8][NTH];
    __shared__ float2 rotU[8][4];
    __shared__ float2 vwU[8][4];
    __shared__ float  pco[7][6];
    __shared__ float  pwh[16];
    __shared__ float  wsum[NTH / 32][8];
    __shared__ unsigned int lastflag;

    const int blk = blockIdx.x, tid = threadIdx.x;
    const int batch = blk >> 3, br1 = (blk >> 1) & 3, b2 = (blk & 1) * 2;

    float2 r[8];
    const float2 Z = make_float2(0.0f, 0.0f);
    r[0] = make_float2(tid == 0 ? 1.0f : 0.0f, 0.0f);
#pragma unroll
    for (int a = 1; a < 8; ++a) r[a] = Z;

    simLayer<0, 4>(r, buf, x, batch, w, pw, rotU, vwU, pco, pwh);
    // compact: keep layer-1 branch br1, reset ancillas to |00>
    r[0] = r[br1]; r[1] = r[2] = r[3] = Z;
    simLayer<1, 4>(r, buf, x, batch, w, pw, rotU, vwU, pco, pwh);
    // split: carry layer-2 branches b2 and b2+1 simultaneously
    {
        float2 t0 = r[b2], t1 = r[b2 + 1];
        r[0] = t0; r[4] = t1;
        r[1] = r[2] = r[3] = r[5] = r[6] = r[7] = Z;
    }
    simLayer<2, 8>(r, buf, x, batch, w, pw, rotU, vwU, pco, pwh);

    // EV partials: Z-signs depend only on tid bits 0..7; trace over anc bits
    // and both carried branches (fixed order -> deterministic)
    float tot = 0.0f;
#pragma unroll
    for (int a = 0; a < 8; ++a)
        tot += r[a].x * r[a].x + r[a].y * r[a].y;

    const int wid = tid >> 5, lane = tid & 31;
#pragma unroll
    for (int q = 0; q < 8; ++q) {
        float v = ((tid >> q) & 1) ? -tot : tot;
#pragma unroll
        for (int o = 16; o > 0; o >>= 1) v += __shfl_down_sync(0xffffffffu, v, o);
        if (lane == 0) wsum[wid][q] = v;
    }
    __syncthreads();
    if (tid < 8) {
        float s = 0.0f;
#pragma unroll
        for (int wgi = 0; wgi < NTH / 32; ++wgi) s += wsum[wgi][tid];
        g_ev[blk * 8 + tid] = s;
    }

    // last CTA per batch reduces the 8 partials (fixed order -> deterministic).
    // Monotonic ticket, never reset -> graph-replay safe (8 arrivals/launch).
    __threadfence();
    __syncthreads();
    if (tid == 0) {
        unsigned int old = atomicAdd(&g_tk[batch], 1u);
        lastflag = ((old & 7u) == 7u);
    }
    __syncthreads();
    if (lastflag) {
        __threadfence();
        if (tid < 8) {
            float s = 0.0f;
#pragma unroll
            for (int k = 0; k < 8; ++k) s += g_ev[(batch * 8 + k) * 8 + tid];
            out[batch * 8 + tid] = s;
        }
    }
}

extern "C" void kernel_launch(void* const* d_in, const int* in_sizes, int n_in,
                              void* d_out, int out_size) {
    const float* x  = (const float*)d_in[0];   // (16, 8)
    const float* w  = (const float*)d_in[1];   // (3, 48)
    const float* pw = (const float*)d_in[2];   // (3, 2, 8)
    float* out = (float*)d_out;                // (16, 8)
    (void)in_sizes; (void)n_in; (void)out_size;

    qpie_all<<<128, NTH>>>(x, w, pw, out);
}